// round 1
// baseline (speedup 1.0000x reference)
#include <cuda_runtime.h>
#include <cuda_bf16.h>

// BahdanauAttention: context[b,d] = sum_t softmax_t( V·tanh(values[b,t]@W1 + (query[b]@W2 + b2) + b1) ) * values[b,t,d]
// B=16, T=8192, D=256, U=256, fp32 in/out.
// Strategy: tf32 mma.sync GEMM for values@W1 with fused tanh/V epilogue -> scores,
// then softmax stats, then weights + context (second values pass).

#define Bn 16
#define Tn 8192
#define Dn 256
#define Un 256
#define NCH 32          // context chunks per batch (chunk = 256 rows)

// Scratch (allocation-free rule: __device__ globals)
__device__ float g_scores[Bn * Tn];          // 512 KB
__device__ float g_biasq[Bn * Un];           // W1_b + query@W2 + W2_b
__device__ float g_stats[2 * Bn];            // (max, sumexp) per batch
__device__ float g_partial[Bn * NCH * Dn];   // 512 KB context partials

// ---------------- helpers ----------------

__device__ __forceinline__ unsigned f2tf(float f) {
    unsigned r;
    asm("cvt.rna.tf32.f32 %0, %1;" : "=r"(r) : "f"(f));
    return r;
}

__device__ __forceinline__ void mma_tf32(float* c, const unsigned* a, unsigned b0, unsigned b1) {
    asm volatile(
        "mma.sync.aligned.m16n8k8.row.col.f32.tf32.tf32.f32 "
        "{%0,%1,%2,%3},{%4,%5,%6,%7},{%8,%9},{%0,%1,%2,%3};"
        : "+f"(c[0]), "+f"(c[1]), "+f"(c[2]), "+f"(c[3])
        : "r"(a[0]), "r"(a[1]), "r"(a[2]), "r"(a[3]), "r"(b0), "r"(b1));
}

// Accurate-enough tanh: 1 - 2/(exp(2x)+1). __expf ~2ulp, __fdividef ~2ulp -> err ~1e-6.
// Saturates correctly at +/-1 for large |x| (exp underflow/overflow handled).
__device__ __forceinline__ float tanh_fast(float x) {
    float e = __expf(2.0f * x);
    return 1.0f - __fdividef(2.0f, e + 1.0f);
}

// ---------------- kernel 0: biasq[b,u] = W1_b[u] + W2_b[u] + query[b,:]@W2[:,u] ----------------

__global__ void projq_kernel(const float* __restrict__ query, const float* __restrict__ W2,
                             const float* __restrict__ W2b, const float* __restrict__ W1b) {
    int u = threadIdx.x, b = blockIdx.x;
    const float* q = query + b * Dn;
    float s = W2b[u];
#pragma unroll 4
    for (int d = 0; d < Dn; ++d) s += q[d] * W2[d * Un + u];
    g_biasq[b * Un + u] = s + W1b[u];
}

// ---------------- kernel 1: scores via tf32 mma, fused tanh*V epilogue ----------------
// Block: 128 threads (4 warps), tile M=128 (t rows), K=256 (D), N=256 (U).
// Warp w owns rows [32w, 32w+32) as two m16 tiles. N processed in 4 chunks of 64 (8 n-tiles).
// A tile (values, tf32) and W1 chunk (tf32) staged in dynamic smem with conflict-free strides.

#define SA_STRIDE 260                      // 260 % 32 == 4 -> conflict-free A frag loads
#define SW_STRIDE 72                       // 72 % 32 == 8 -> conflict-free B frag loads
#define SMEM_A_WORDS (128 * SA_STRIDE)     // 33280
#define SMEM_W_WORDS (256 * SW_STRIDE)     // 18432
#define SMEM_TOTAL_BYTES ((SMEM_A_WORDS + SMEM_W_WORDS + 256 + 256) * 4)  // 208896 B

__global__ __launch_bounds__(128, 1)
void score_kernel(const float* __restrict__ values, const float* __restrict__ W1,
                  const float* __restrict__ Vw) {
    extern __shared__ unsigned smemu[];
    unsigned* sA = smemu;
    unsigned* sW = smemu + SMEM_A_WORDS;
    float* sBQ = (float*)(smemu + SMEM_A_WORDS + SMEM_W_WORDS);
    float* sVW = sBQ + 256;

    int tid = threadIdx.x;
    int b = blockIdx.x >> 6;            // 64 blocks per batch
    int t0 = (blockIdx.x & 63) * 128;
    int mw = tid >> 5;                  // warp id = M-warp
    int lane = tid & 31;
    int g = lane >> 2, tig = lane & 3;  // mma group / thread-in-group

    // Stage A tile (values rows t0..t0+127, all D) as tf32
    const float* vbase = values + ((size_t)b * Tn + t0) * Dn;
    for (int i = tid; i < 128 * 256; i += 128) {
        int r = i >> 8, c = i & 255;
        sA[r * SA_STRIDE + c] = f2tf(vbase[i]);
    }
    for (int i = tid; i < 256; i += 128) {
        sBQ[i] = g_biasq[b * Un + i];
        sVW[i] = Vw[i];
    }

    float rowsum[2][2] = {{0.f, 0.f}, {0.f, 0.f}};  // [mtile][row g / g+8]

    for (int nc = 0; nc < 4; ++nc) {
        __syncthreads();  // A tile visible (first iter); prior sW consumption done (later iters)
        // Stage W1 chunk: cols [nc*64, nc*64+64)
        for (int i = tid; i < 256 * 64; i += 128) {
            int r = i >> 6, c = i & 63;
            sW[r * SW_STRIDE + c] = f2tf(W1[r * Un + nc * 64 + c]);
        }
        __syncthreads();

        float acc[2][8][4];
#pragma unroll
        for (int mt = 0; mt < 2; ++mt)
#pragma unroll
            for (int nt = 0; nt < 8; ++nt)
#pragma unroll
                for (int q = 0; q < 4; ++q) acc[mt][nt][q] = 0.f;

#pragma unroll 2
        for (int kk = 0; kk < 32; ++kk) {
            int kb = kk * 8;
            unsigned a[2][4];
#pragma unroll
            for (int mt = 0; mt < 2; ++mt) {
                int r0 = mw * 32 + mt * 16 + g;
                a[mt][0] = sA[r0 * SA_STRIDE + kb + tig];
                a[mt][1] = sA[(r0 + 8) * SA_STRIDE + kb + tig];
                a[mt][2] = sA[r0 * SA_STRIDE + kb + tig + 4];
                a[mt][3] = sA[(r0 + 8) * SA_STRIDE + kb + tig + 4];
            }
#pragma unroll
            for (int nt = 0; nt < 8; ++nt) {
                unsigned b0 = sW[(kb + tig) * SW_STRIDE + nt * 8 + g];
                unsigned b1 = sW[(kb + tig + 4) * SW_STRIDE + nt * 8 + g];
                mma_tf32(acc[0][nt], a[0], b0, b1);
                mma_tf32(acc[1][nt], a[1], b0, b1);
            }
        }

        // Epilogue: tanh(p + biasq) * Vw, reduce over this n-chunk into rowsum regs.
        // acc layout: c0=(row g, col 2tig), c1=(g, 2tig+1), c2=(g+8, 2tig), c3=(g+8, 2tig+1)
#pragma unroll
        for (int nt = 0; nt < 8; ++nt) {
            int c = nc * 64 + nt * 8 + 2 * tig;
            float bq0 = sBQ[c], bq1 = sBQ[c + 1];
            float vw0 = sVW[c], vw1 = sVW[c + 1];
#pragma unroll
            for (int mt = 0; mt < 2; ++mt) {
                rowsum[mt][0] += tanh_fast(acc[mt][nt][0] + bq0) * vw0
                               + tanh_fast(acc[mt][nt][1] + bq1) * vw1;
                rowsum[mt][1] += tanh_fast(acc[mt][nt][2] + bq0) * vw0
                               + tanh_fast(acc[mt][nt][3] + bq1) * vw1;
            }
        }
    }

    // Reduce partial row sums across the 4-lane quad (tig 0..3), write scores.
#pragma unroll
    for (int mt = 0; mt < 2; ++mt)
#pragma unroll
        for (int j = 0; j < 2; ++j) {
            float v = rowsum[mt][j];
            v += __shfl_xor_sync(0xffffffffu, v, 1);
            v += __shfl_xor_sync(0xffffffffu, v, 2);
            rowsum[mt][j] = v;
        }
    if (tig == 0) {
        int rbase = t0 + mw * 32;
#pragma unroll
        for (int mt = 0; mt < 2; ++mt) {
            g_scores[b * Tn + rbase + mt * 16 + g] = rowsum[mt][0];
            g_scores[b * Tn + rbase + mt * 16 + g + 8] = rowsum[mt][1];
        }
    }
}

// ---------------- kernel 2: per-batch softmax stats (max, sumexp) ----------------

__global__ void stats_kernel() {
    int b = blockIdx.x, tid = threadIdx.x;
    __shared__ float red[32];
    const float* sc = g_scores + b * Tn;

    float m = -3.4e38f;
    for (int i = tid; i < Tn; i += 256) m = fmaxf(m, sc[i]);
#pragma unroll
    for (int o = 16; o; o >>= 1) m = fmaxf(m, __shfl_xor_sync(0xffffffffu, m, o));
    if ((tid & 31) == 0) red[tid >> 5] = m;
    __syncthreads();
    if (tid < 32) {
        float v = (tid < 8) ? red[tid] : -3.4e38f;
#pragma unroll
        for (int o = 4; o; o >>= 1) v = fmaxf(v, __shfl_xor_sync(0xffffffffu, v, o));
        if (tid == 0) red[0] = v;
    }
    __syncthreads();
    m = red[0];
    __syncthreads();

    float s = 0.f;
    for (int i = tid; i < Tn; i += 256) s += __expf(sc[i] - m);
#pragma unroll
    for (int o = 16; o; o >>= 1) s += __shfl_xor_sync(0xffffffffu, s, o);
    if ((tid & 31) == 0) red[tid >> 5] = s;
    __syncthreads();
    if (tid == 0) {
        float z = 0.f;
#pragma unroll
        for (int w = 0; w < 8; ++w) z += red[w];
        g_stats[2 * b] = m;
        g_stats[2 * b + 1] = z;
    }
}

// ---------------- kernel 3: weights out + per-chunk context partials ----------------
// grid (NCH, B), 256 threads; thread d accumulates column d over 256 t's.

__global__ void ctx_kernel(const float* __restrict__ values, float* __restrict__ wout) {
    int ch = blockIdx.x, b = blockIdx.y, tid = threadIdx.x;
    __shared__ float ws[256];
    float m = g_stats[2 * b];
    float invZ = 1.0f / g_stats[2 * b + 1];
    int t0 = ch * 256;

    float w = __expf(g_scores[b * Tn + t0 + tid] - m) * invZ;
    ws[tid] = w;
    wout[b * Tn + t0 + tid] = w;
    __syncthreads();

    const float* vp = values + ((size_t)b * Tn + t0) * Dn + tid;
    float acc = 0.f;
#pragma unroll 8
    for (int t = 0; t < 256; ++t) acc += ws[t] * vp[(size_t)t * Dn];
    g_partial[(b * NCH + ch) * Dn + tid] = acc;
}

// ---------------- kernel 4: reduce context partials ----------------

__global__ void reduce_kernel(float* __restrict__ ctx_out) {
    int b = blockIdx.x, d = threadIdx.x;
    const float* p = g_partial + b * NCH * Dn + d;
    float s = 0.f;
#pragma unroll
    for (int c = 0; c < NCH; ++c) s += p[c * Dn];
    ctx_out[b * Dn + d] = s;
}

// ---------------- launch ----------------

extern "C" void kernel_launch(void* const* d_in, const int* in_sizes, int n_in,
                              void* d_out, int out_size) {
    const float* values = (const float*)d_in[0];
    const float* query  = (const float*)d_in[1];
    const float* W1w    = (const float*)d_in[2];
    const float* W1b    = (const float*)d_in[3];
    const float* W2w    = (const float*)d_in[4];
    const float* W2b    = (const float*)d_in[5];
    const float* Vw     = (const float*)d_in[6];
    // d_in[7] = V_b: constant shift on scores -> softmax-invariant; weights and
    // context are unchanged, so it is intentionally unused.
    (void)in_sizes; (void)n_in; (void)out_size;

    float* ctx_out = (float*)d_out;             // [B, D]
    float* w_out   = (float*)d_out + Bn * Dn;   // [B, T, 1]

    cudaFuncSetAttribute(score_kernel, cudaFuncAttributeMaxDynamicSharedMemorySize,
                         SMEM_TOTAL_BYTES);

    projq_kernel<<<Bn, Un>>>(query, W2w, W2b, W1b);
    score_kernel<<<Bn * (Tn / 128), 128, SMEM_TOTAL_BYTES>>>(values, W1w, Vw);
    stats_kernel<<<Bn, 256>>>();
    ctx_kernel<<<dim3(NCH, Bn), 256>>>(values, w_out);
    reduce_kernel<<<Bn, Dn>>>(ctx_out);
}

// round 3
// speedup vs baseline: 3.6646x; 3.6646x over previous
#include <cuda_runtime.h>
#include <cuda_fp16.h>
#include <cstdint>
#include <cstddef>

// BahdanauAttention B=16, T=8192, D=256, U=256 fp32.
// Baseline-PTX build (ptxas target sm_100, no 'a' features): mma.sync fp16 GEMM,
// 512-thread CTAs, full-resident A/B tiles in smem, fused tanh.approx*V epilogue.

#define Bn 16
#define Tn 8192
#define Dn 256
#define Un 256
#define CCH 64          // ctx chunks (128 rows each)

__device__ float g_scores[Bn * Tn];
__device__ float g_biasq[Bn * Un];
__device__ float g_stats[2 * Bn];
__device__ float g_partial[Bn * CCH * Dn];

// ---------------- helpers ----------------

__device__ __forceinline__ float tanh_fast(float x) {
    float y;
    asm("tanh.approx.f32 %0, %1;" : "=f"(y) : "f"(x));
    return y;
}

__device__ __forceinline__ uint32_t pack_half2(float x, float y) {
    __half2 h = __floats2half2_rn(x, y);
    return *(uint32_t*)&h;
}

__device__ __forceinline__ void mma_fp16(float* c, const uint32_t* a, uint32_t b0, uint32_t b1) {
    asm volatile(
        "mma.sync.aligned.m16n8k16.row.col.f32.f16.f16.f32 "
        "{%0,%1,%2,%3},{%4,%5,%6,%7},{%8,%9},{%0,%1,%2,%3};"
        : "+f"(c[0]), "+f"(c[1]), "+f"(c[2]), "+f"(c[3])
        : "r"(a[0]), "r"(a[1]), "r"(a[2]), "r"(a[3]), "r"(b0), "r"(b1));
}

// ---------------- smem layout (bytes) for score kernel ----------------
// A: 128 rows x 132 words (word = half2 of k-pair)  = 67584 B
// B: 256 u-rows x 132 words                          = 135168 B
// stride 132 (== 4 mod 32) -> fragment LDS bank = 4*g + tig : conflict-free.
#define SAW 132
#define SM_A 0
#define SM_B 67584
#define SM_BQ 202752
#define SM_VW 203776
#define SM_SROW 204800
#define SM_TOTAL 206848

// ---------------- kernel 0: biasq[b,u] = W1_b + W2_b + query@W2 ----------------

__global__ void projq_kernel(const float* __restrict__ query, const float* __restrict__ W2,
                             const float* __restrict__ W2b, const float* __restrict__ W1b) {
    int u = threadIdx.x, b = blockIdx.x;
    const float* q = query + b * Dn;
    float s = W2b[u];
#pragma unroll 4
    for (int d = 0; d < Dn; ++d) s += q[d] * W2[d * Un + u];
    g_biasq[b * Un + u] = s + W1b[u];
}

// ---------------- kernel 1: scores via fp16 mma.sync ----------------
// Grid 1024 CTAs (16 b x 64 tiles of 128 t-rows), 512 threads (16 warps).
// Warp (mwarp = wid&3, nwarp = wid>>2): tile M=32 (2 mtiles), N=64 (8 ntiles), K=256.

__global__ __launch_bounds__(512, 1)
void score_kernel(const float* __restrict__ values, const float* __restrict__ W1,
                  const float* __restrict__ Vw) {
    extern __shared__ char smem[];
    uint32_t* sA = (uint32_t*)(smem + SM_A);
    uint32_t* sB = (uint32_t*)(smem + SM_B);
    float* sBQ = (float*)(smem + SM_BQ);
    float* sVW = (float*)(smem + SM_VW);
    float* srow = (float*)(smem + SM_SROW);

    const int tid = threadIdx.x;
    const int wid = tid >> 5, lane = tid & 31;
    const int mwarp = wid & 3, nwarp = wid >> 2;
    const int g = lane >> 2, tig = lane & 3;
    const int b = blockIdx.x >> 6;
    const int t0 = (blockIdx.x & 63) * 128;

    // Stage A: values[t0..t0+127][0..255] -> fp16 pairs, rows of 128 words + pad.
    const float2* v2 = (const float2*)(values + ((size_t)b * Tn + t0) * Dn);
#pragma unroll 4
    for (int i = tid; i < 128 * 128; i += 512) {
        int r = i >> 7, c2 = i & 127;
        float2 x = v2[i];
        sA[r * SAW + c2] = pack_half2(x.x, x.y);
    }

    // Stage B: W1[k][u] -> sB[u][k-pair]. lane==u gives conflict-limited STS (one-time).
#pragma unroll 4
    for (int i = tid; i < 256 * 128; i += 512) {
        int u = i & 255, kp = i >> 8;
        float x0 = W1[(size_t)(2 * kp) * Un + u];
        float x1 = W1[(size_t)(2 * kp + 1) * Un + u];
        sB[u * SAW + kp] = pack_half2(x0, x1);
    }

    if (tid < 256) {
        sBQ[tid] = g_biasq[b * Un + tid];
        sVW[tid] = Vw[tid];
    }
    __syncthreads();

    float acc[2][8][4];
#pragma unroll
    for (int mt = 0; mt < 2; ++mt)
#pragma unroll
        for (int nt = 0; nt < 8; ++nt)
#pragma unroll
            for (int q = 0; q < 4; ++q) acc[mt][nt][q] = 0.f;

    const int r0 = mwarp * 32 + g;
    const int u0 = nwarp * 64 + g;

#pragma unroll
    for (int ks = 0; ks < 16; ++ks) {
        const int kb = ks * 8;
        uint32_t a[2][4];
#pragma unroll
        for (int mt = 0; mt < 2; ++mt) {
            int r = r0 + mt * 16;
            a[mt][0] = sA[r * SAW + kb + tig];
            a[mt][1] = sA[(r + 8) * SAW + kb + tig];
            a[mt][2] = sA[r * SAW + kb + tig + 4];
            a[mt][3] = sA[(r + 8) * SAW + kb + tig + 4];
        }
#pragma unroll
        for (int nt = 0; nt < 8; ++nt) {
            uint32_t b0 = sB[(u0 + nt * 8) * SAW + kb + tig];
            uint32_t b1 = sB[(u0 + nt * 8) * SAW + kb + tig + 4];
            mma_fp16(acc[0][nt], a[0], b0, b1);
            mma_fp16(acc[1][nt], a[1], b0, b1);
        }
    }

    // Epilogue: tanh(p + biasq) * Vw, reduced over this warp's 64 cols.
    float rowsum[2][2] = {{0.f, 0.f}, {0.f, 0.f}};
#pragma unroll
    for (int nt = 0; nt < 8; ++nt) {
        int c = nwarp * 64 + nt * 8 + 2 * tig;
        float bq0 = sBQ[c], bq1 = sBQ[c + 1];
        float vw0 = sVW[c], vw1 = sVW[c + 1];
#pragma unroll
        for (int mt = 0; mt < 2; ++mt) {
            rowsum[mt][0] += tanh_fast(acc[mt][nt][0] + bq0) * vw0
                           + tanh_fast(acc[mt][nt][1] + bq1) * vw1;
            rowsum[mt][1] += tanh_fast(acc[mt][nt][2] + bq0) * vw0
                           + tanh_fast(acc[mt][nt][3] + bq1) * vw1;
        }
    }

    // Quad-reduce over tig, stash per-nwarp partials, cross-warp sum.
#pragma unroll
    for (int mt = 0; mt < 2; ++mt)
#pragma unroll
        for (int j = 0; j < 2; ++j) {
            float v = rowsum[mt][j];
            v += __shfl_xor_sync(0xffffffffu, v, 1);
            v += __shfl_xor_sync(0xffffffffu, v, 2);
            rowsum[mt][j] = v;
        }
    if (tig == 0) {
#pragma unroll
        for (int mt = 0; mt < 2; ++mt) {
            int row = mwarp * 32 + mt * 16 + g;
            srow[row * 4 + nwarp] = rowsum[mt][0];
            srow[(row + 8) * 4 + nwarp] = rowsum[mt][1];
        }
    }
    __syncthreads();
    if (tid < 128) {
        float4 s4 = ((const float4*)srow)[tid];
        g_scores[b * Tn + t0 + tid] = s4.x + s4.y + s4.z + s4.w;
    }
}

// ---------------- kernel 2: per-batch softmax stats ----------------

__global__ void stats_kernel() {
    int b = blockIdx.x, tid = threadIdx.x;
    __shared__ float red[32];
    const float* sc = g_scores + b * Tn;

    float m = -3.4e38f;
    for (int i = tid; i < Tn; i += 256) m = fmaxf(m, sc[i]);
#pragma unroll
    for (int o = 16; o; o >>= 1) m = fmaxf(m, __shfl_xor_sync(0xffffffffu, m, o));
    if ((tid & 31) == 0) red[tid >> 5] = m;
    __syncthreads();
    if (tid < 32) {
        float v = (tid < 8) ? red[tid] : -3.4e38f;
#pragma unroll
        for (int o = 4; o; o >>= 1) v = fmaxf(v, __shfl_xor_sync(0xffffffffu, v, o));
        if (tid == 0) red[0] = v;
    }
    __syncthreads();
    m = red[0];
    __syncthreads();

    float s = 0.f;
    for (int i = tid; i < Tn; i += 256) s += __expf(sc[i] - m);
#pragma unroll
    for (int o = 16; o; o >>= 1) s += __shfl_xor_sync(0xffffffffu, s, o);
    if ((tid & 31) == 0) red[tid >> 5] = s;
    __syncthreads();
    if (tid == 0) {
        float z = 0.f;
#pragma unroll
        for (int w = 0; w < 8; ++w) z += red[w];
        g_stats[2 * b] = m;
        g_stats[2 * b + 1] = z;
    }
}

// ---------------- kernel 3: weights + context partials ----------------
// grid (CCH, B), 256 threads: 4 groups of 64; group handles 32 rows, float4 over d.

__global__ __launch_bounds__(256)
void ctx_kernel(const float* __restrict__ values, float* __restrict__ wout) {
    int ch = blockIdx.x, b = blockIdx.y, tid = threadIdx.x;
    __shared__ float ws[128];
    __shared__ float4 spart[3][64];
    float m = g_stats[2 * b];
    float invZ = 1.0f / g_stats[2 * b + 1];
    int t0 = ch * 128;

    if (tid < 128) {
        float w = __expf(g_scores[b * Tn + t0 + tid] - m) * invZ;
        ws[tid] = w;
        wout[b * Tn + t0 + tid] = w;
    }
    __syncthreads();

    int g2 = tid >> 6, l64 = tid & 63;
    const float4* vp = (const float4*)(values + ((size_t)b * Tn + t0) * Dn);
    float4 acc = make_float4(0.f, 0.f, 0.f, 0.f);
#pragma unroll 8
    for (int i = 0; i < 32; ++i) {
        int t = g2 * 32 + i;
        float w = ws[t];
        float4 v = vp[(size_t)t * 64 + l64];
        acc.x += w * v.x; acc.y += w * v.y; acc.z += w * v.z; acc.w += w * v.w;
    }
    if (g2 > 0) spart[g2 - 1][l64] = acc;
    __syncthreads();
    if (g2 == 0) {
#pragma unroll
        for (int j = 0; j < 3; ++j) {
            float4 p = spart[j][l64];
            acc.x += p.x; acc.y += p.y; acc.z += p.z; acc.w += p.w;
        }
        *(float4*)(g_partial + ((size_t)(b * CCH + ch)) * Dn + 4 * l64) = acc;
    }
}

// ---------------- kernel 4: reduce partials ----------------

__global__ void reduce_kernel(float* __restrict__ ctx_out) {
    int b = blockIdx.x, d = threadIdx.x;
    const float* p = g_partial + b * CCH * Dn + d;
    float s = 0.f;
#pragma unroll
    for (int c = 0; c < CCH; ++c) s += p[c * Dn];
    ctx_out[b * Dn + d] = s;
}

// ---------------- launch ----------------

extern "C" void kernel_launch(void* const* d_in, const int* in_sizes, int n_in,
                              void* d_out, int out_size) {
    const float* values = (const float*)d_in[0];
    const float* query  = (const float*)d_in[1];
    const float* W1w    = (const float*)d_in[2];
    const float* W1b    = (const float*)d_in[3];
    const float* W2w    = (const float*)d_in[4];
    const float* W2b    = (const float*)d_in[5];
    const float* Vw     = (const float*)d_in[6];
    // d_in[7] = V_b: softmax-invariant constant, intentionally unused.
    (void)in_sizes; (void)n_in; (void)out_size;

    float* ctx_out = (float*)d_out;             // [B, D]
    float* w_out   = (float*)d_out + Bn * Dn;   // [B, T, 1]

    cudaFuncSetAttribute(score_kernel, cudaFuncAttributeMaxDynamicSharedMemorySize, SM_TOTAL);

    projq_kernel<<<Bn, Un>>>(query, W2w, W2b, W1b);
    score_kernel<<<Bn * (Tn / 128), 512, SM_TOTAL>>>(values, W1w, Vw);
    stats_kernel<<<Bn, 256>>>();
    ctx_kernel<<<dim3(CCH, Bn), 256>>>(values, w_out);
    reduce_kernel<<<Bn, Dn>>>(ctx_out);
}

// round 4
// speedup vs baseline: 4.2848x; 1.1692x over previous
#include <cuda_runtime.h>
#include <cuda_fp16.h>
#include <cstdint>
#include <cstddef>

// BahdanauAttention B=16, T=8192, D=256, U=256 fp32.
// Baseline-PTX build (ptxas sm_100, no 'a' features): fp16 mma.sync + ldmatrix,
// persistent score kernel (W1 staged once per CTA), fused tanh.approx*V epilogue.

#define Bn 16
#define Tn 8192
#define Dn 256
#define Un 256
#define CCH 64          // ctx chunks (128 rows each)
#define NTILES (Bn * (Tn / 128))   // 1024 score tiles

__device__ float g_scores[Bn * Tn];
__device__ float g_biasq[Bn * Un];
__device__ float g_Z[Bn];
__device__ float g_partial[Bn * CCH * Dn];

// ---------------- helpers ----------------

__device__ __forceinline__ float tanh_fast(float x) {
    float y;
    asm("tanh.approx.f32 %0, %1;" : "=f"(y) : "f"(x));
    return y;
}

__device__ __forceinline__ uint32_t pack_half2(float x, float y) {
    __half2 h = __floats2half2_rn(x, y);
    return *(uint32_t*)&h;
}

__device__ __forceinline__ uint32_t smem_u32(const void* p) {
    uint32_t a;
    asm("{ .reg .u64 t; cvta.to.shared.u64 t, %1; cvt.u32.u64 %0, t; }" : "=r"(a) : "l"(p));
    return a;
}

__device__ __forceinline__ void mma_fp16(float* c, const uint32_t* a, uint32_t b0, uint32_t b1) {
    asm volatile(
        "mma.sync.aligned.m16n8k16.row.col.f32.f16.f16.f32 "
        "{%0,%1,%2,%3},{%4,%5,%6,%7},{%8,%9},{%0,%1,%2,%3};"
        : "+f"(c[0]), "+f"(c[1]), "+f"(c[2]), "+f"(c[3])
        : "r"(a[0]), "r"(a[1]), "r"(a[2]), "r"(a[3]), "r"(b0), "r"(b1));
}

#define LDSM4(r, addr) \
    asm volatile("ldmatrix.sync.aligned.m8n8.x4.shared.b16 {%0,%1,%2,%3}, [%4];" \
                 : "=r"((r)[0]), "=r"((r)[1]), "=r"((r)[2]), "=r"((r)[3]) : "r"(addr))

// ---------------- smem layout (bytes) for score kernel ----------------
// A: 128 rows x 132 words (half2 per word)  = 67584 B
// B: 256 u-rows x 132 words                 = 135168 B
// stride 132 words (4 mod 32): ldmatrix row step = 4 banks -> conflict-free.
#define SAW 132
#define SM_A 0
#define SM_B 67584
#define SM_BQ 202752
#define SM_VW 203776
#define SM_SROW 204800
#define SM_TOTAL 206848

// ---------------- kernel 0: biasq[b,u] = W1_b + W2_b + query@W2 ----------------

__global__ void projq_kernel(const float* __restrict__ query, const float* __restrict__ W2,
                             const float* __restrict__ W2b, const float* __restrict__ W1b) {
    int u = threadIdx.x, b = blockIdx.x;
    const float* q = query + b * Dn;
    float s = W2b[u];
#pragma unroll 4
    for (int d = 0; d < Dn; ++d) s += q[d] * W2[d * Un + u];
    g_biasq[b * Un + u] = s + W1b[u];
}

// ---------------- kernel 1: persistent score kernel ----------------
// Grid 148 CTAs x 512 threads (16 warps). Each CTA: stage W1 once, loop ~7 tiles.
// Per tile: M=128 t-rows, K=256, N=256. Warp (mwarp=wid&3, nwarp=wid>>2):
// 2 mtiles x 8 ntiles of m16n8k16. Fragments via ldmatrix.x4.

__global__ __launch_bounds__(512, 1)
void score_kernel(const float* __restrict__ values, const float* __restrict__ W1,
                  const float* __restrict__ Vw) {
    extern __shared__ char smem[];
    uint32_t* sA = (uint32_t*)(smem + SM_A);
    uint32_t* sB = (uint32_t*)(smem + SM_B);
    float* sBQ = (float*)(smem + SM_BQ);
    float* sVW = (float*)(smem + SM_VW);
    float* srow = (float*)(smem + SM_SROW);

    const int tid = threadIdx.x;
    const int wid = tid >> 5, lane = tid & 31;
    const int mwarp = wid & 3, nwarp = wid >> 2;
    const int g = lane >> 2, tig = lane & 3;

    // Stage B once: W1[k][u] -> sB[u][kp] as half2(k-pair).
#pragma unroll 4
    for (int i = tid; i < 256 * 128; i += 512) {
        int u = i & 255, kp = i >> 8;
        float x0 = W1[(size_t)(2 * kp) * Un + u];
        float x1 = W1[(size_t)(2 * kp + 1) * Un + u];
        sB[u * SAW + kp] = pack_half2(x0, x1);
    }
    if (tid < 256) sVW[tid] = Vw[tid];

    // ldmatrix per-lane base addresses.
    const uint32_t sbA = smem_u32(sA), sbB = smem_u32(sB);
    const int t4 = lane >> 3, row_in = lane & 7;   // tile index, row within tile
    // A tiles: rows r0 + (t&1)*8 + row_in, word col (t>>1)*4
    uint32_t adA[2];
#pragma unroll
    for (int mt = 0; mt < 2; ++mt) {
        int r = mwarp * 32 + mt * 16 + ((t4 & 1) << 3) + row_in;
        adA[mt] = sbA + (uint32_t)((r * SAW + ((t4 >> 1) << 2)) << 2);
    }
    // B tiles: rows u0 + np*16 + (t>>1)*8 + row_in, word col (t&1)*4
    uint32_t adB[4];
#pragma unroll
    for (int np = 0; np < 4; ++np) {
        int u = nwarp * 64 + np * 16 + ((t4 >> 1) << 3) + row_in;
        adB[np] = sbB + (uint32_t)((u * SAW + ((t4 & 1) << 2)) << 2);
    }

    for (int tile = blockIdx.x; tile < NTILES; tile += gridDim.x) {
        const int b = tile >> 6;
        const int t0 = (tile & 63) * 128;

        __syncthreads();  // previous tile's sA/sBQ/srow fully consumed

        // Stage A: values[t0..t0+127][:] as half2 pairs.
        const float2* v2 = (const float2*)(values + ((size_t)b * Tn + t0) * Dn);
#pragma unroll 4
        for (int i = tid; i < 128 * 128; i += 512) {
            int r = i >> 7, c2 = i & 127;
            float2 x = v2[i];
            sA[r * SAW + c2] = pack_half2(x.x, x.y);
        }
        if (tid < 256) sBQ[tid] = g_biasq[b * Un + tid];
        __syncthreads();

        float acc[2][8][4];
#pragma unroll
        for (int mt = 0; mt < 2; ++mt)
#pragma unroll
            for (int nt = 0; nt < 8; ++nt)
#pragma unroll
                for (int q = 0; q < 4; ++q) acc[mt][nt][q] = 0.f;

#pragma unroll
        for (int ks = 0; ks < 16; ++ks) {
            const uint32_t ko = (uint32_t)ks * 32;  // 8 words = 32 bytes per k-step
            uint32_t a0[4], a1[4];
            LDSM4(a0, adA[0] + ko);
            LDSM4(a1, adA[1] + ko);
#pragma unroll
            for (int np = 0; np < 4; ++np) {
                uint32_t bb[4];
                LDSM4(bb, adB[np] + ko);
                mma_fp16(acc[0][2 * np], a0, bb[0], bb[1]);
                mma_fp16(acc[1][2 * np], a1, bb[0], bb[1]);
                mma_fp16(acc[0][2 * np + 1], a0, bb[2], bb[3]);
                mma_fp16(acc[1][2 * np + 1], a1, bb[2], bb[3]);
            }
        }

        // Epilogue: tanh(p + biasq) * Vw, reduce over this warp's 64 cols.
        float rowsum[2][2] = {{0.f, 0.f}, {0.f, 0.f}};
#pragma unroll
        for (int nt = 0; nt < 8; ++nt) {
            int c = nwarp * 64 + nt * 8 + 2 * tig;
            float bq0 = sBQ[c], bq1 = sBQ[c + 1];
            float vw0 = sVW[c], vw1 = sVW[c + 1];
#pragma unroll
            for (int mt = 0; mt < 2; ++mt) {
                rowsum[mt][0] += tanh_fast(acc[mt][nt][0] + bq0) * vw0
                               + tanh_fast(acc[mt][nt][1] + bq1) * vw1;
                rowsum[mt][1] += tanh_fast(acc[mt][nt][2] + bq0) * vw0
                               + tanh_fast(acc[mt][nt][3] + bq1) * vw1;
            }
        }
#pragma unroll
        for (int mt = 0; mt < 2; ++mt)
#pragma unroll
            for (int j = 0; j < 2; ++j) {
                float v = rowsum[mt][j];
                v += __shfl_xor_sync(0xffffffffu, v, 1);
                v += __shfl_xor_sync(0xffffffffu, v, 2);
                rowsum[mt][j] = v;
            }
        if (tig == 0) {
#pragma unroll
            for (int mt = 0; mt < 2; ++mt) {
                int row = mwarp * 32 + mt * 16 + g;
                srow[row * 4 + nwarp] = rowsum[mt][0];
                srow[(row + 8) * 4 + nwarp] = rowsum[mt][1];
            }
        }
        __syncthreads();
        if (tid < 128) {
            float4 s4 = ((const float4*)srow)[tid];
            g_scores[b * Tn + t0 + tid] = s4.x + s4.y + s4.z + s4.w;
        }
    }
}

// ---------------- kernel 2: per-batch sum of exp (no max pass needed:
// |score| <= sum|Vw| ~ 13, exp stays comfortably inside fp32 range) ----------------

__global__ void stats_kernel() {
    int b = blockIdx.x, tid = threadIdx.x;
    __shared__ float red[8];
    const float* sc = g_scores + b * Tn;

    float s = 0.f;
#pragma unroll 4
    for (int i = tid; i < Tn; i += 256) s += __expf(sc[i]);
#pragma unroll
    for (int o = 16; o; o >>= 1) s += __shfl_xor_sync(0xffffffffu, s, o);
    if ((tid & 31) == 0) red[tid >> 5] = s;
    __syncthreads();
    if (tid == 0) {
        float z = 0.f;
#pragma unroll
        for (int w = 0; w < 8; ++w) z += red[w];
        g_Z[b] = z;
    }
}

// ---------------- kernel 3: weights + context partials ----------------

__global__ __launch_bounds__(256)
void ctx_kernel(const float* __restrict__ values, float* __restrict__ wout) {
    int ch = blockIdx.x, b = blockIdx.y, tid = threadIdx.x;
    __shared__ float ws[128];
    __shared__ float4 spart[3][64];
    float invZ = 1.0f / g_Z[b];
    int t0 = ch * 128;

    if (tid < 128) {
        float w = __expf(g_scores[b * Tn + t0 + tid]) * invZ;
        ws[tid] = w;
        wout[b * Tn + t0 + tid] = w;
    }
    __syncthreads();

    int g2 = tid >> 6, l64 = tid & 63;
    const float4* vp = (const float4*)(values + ((size_t)b * Tn + t0) * Dn);
    float4 acc = make_float4(0.f, 0.f, 0.f, 0.f);
#pragma unroll 8
    for (int i = 0; i < 32; ++i) {
        int t = g2 * 32 + i;
        float w = ws[t];
        float4 v = vp[(size_t)t * 64 + l64];
        acc.x += w * v.x; acc.y += w * v.y; acc.z += w * v.z; acc.w += w * v.w;
    }
    if (g2 > 0) spart[g2 - 1][l64] = acc;
    __syncthreads();
    if (g2 == 0) {
#pragma unroll
        for (int j = 0; j < 3; ++j) {
            float4 p = spart[j][l64];
            acc.x += p.x; acc.y += p.y; acc.z += p.z; acc.w += p.w;
        }
        *(float4*)(g_partial + ((size_t)(b * CCH + ch)) * Dn + 4 * l64) = acc;
    }
}

// ---------------- kernel 4: reduce partials ----------------

__global__ void reduce_kernel(float* __restrict__ ctx_out) {
    int b = blockIdx.x, d = threadIdx.x;
    const float* p = g_partial + b * CCH * Dn + d;
    float s = 0.f;
#pragma unroll
    for (int c = 0; c < CCH; ++c) s += p[c * Dn];
    ctx_out[b * Dn + d] = s;
}

// ---------------- launch ----------------

extern "C" void kernel_launch(void* const* d_in, const int* in_sizes, int n_in,
                              void* d_out, int out_size) {
    const float* values = (const float*)d_in[0];
    const float* query  = (const float*)d_in[1];
    const float* W1w    = (const float*)d_in[2];
    const float* W1b    = (const float*)d_in[3];
    const float* W2w    = (const float*)d_in[4];
    const float* W2b    = (const float*)d_in[5];
    const float* Vw     = (const float*)d_in[6];
    // d_in[7] = V_b: softmax-invariant constant, intentionally unused.
    (void)in_sizes; (void)n_in; (void)out_size;

    float* ctx_out = (float*)d_out;             // [B, D]
    float* w_out   = (float*)d_out + Bn * Dn;   // [B, T, 1]

    cudaFuncSetAttribute(score_kernel, cudaFuncAttributeMaxDynamicSharedMemorySize, SM_TOTAL);

    projq_kernel<<<Bn, Un>>>(query, W2w, W2b, W1b);
    score_kernel<<<148, 512, SM_TOTAL>>>(values, W1w, Vw);
    stats_kernel<<<Bn, 256>>>();
    ctx_kernel<<<dim3(CCH, Bn), 256>>>(values, w_out);
    reduce_kernel<<<Bn, Dn>>>(ctx_out);
}

// round 5
// speedup vs baseline: 5.2480x; 1.2248x over previous
#include <cuda_runtime.h>
#include <cuda_fp16.h>
#include <cstdint>
#include <cstddef>

// BahdanauAttention B=16, T=8192, D=256, U=256 fp32.
// Baseline-PTX (ptxas sm_100): fp16 mma.sync + ldmatrix, persistent score kernel,
// double-buffered A with register prefetch, epilogue emits exp(score).

#define Bn 16
#define Tn 8192
#define Dn 256
#define Un 256
#define CCH 64                      // ctx chunks (128 rows each)
#define TM 64                       // score tile M
#define NTILES (Bn * (Tn / TM))     // 2048
#define GRID_SCORE 148

__device__ float g_escore[Bn * Tn];   // exp(score)
__device__ float g_biasq[Bn * Un];
__device__ float g_Z[Bn];
__device__ float g_partial[Bn * CCH * Dn];

// ---------------- helpers ----------------

__device__ __forceinline__ float tanh_fast(float x) {
    float y;
    asm("tanh.approx.f32 %0, %1;" : "=f"(y) : "f"(x));
    return y;
}

__device__ __forceinline__ uint32_t pack_half2(float x, float y) {
    __half2 h = __floats2half2_rn(x, y);
    return *(uint32_t*)&h;
}

__device__ __forceinline__ uint32_t smem_u32(const void* p) {
    uint32_t a;
    asm("{ .reg .u64 t; cvta.to.shared.u64 t, %1; cvt.u32.u64 %0, t; }" : "=r"(a) : "l"(p));
    return a;
}

__device__ __forceinline__ void mma_fp16(float* c, const uint32_t* a, uint32_t b0, uint32_t b1) {
    asm volatile(
        "mma.sync.aligned.m16n8k16.row.col.f32.f16.f16.f32 "
        "{%0,%1,%2,%3},{%4,%5,%6,%7},{%8,%9},{%0,%1,%2,%3};"
        : "+f"(c[0]), "+f"(c[1]), "+f"(c[2]), "+f"(c[3])
        : "r"(a[0]), "r"(a[1]), "r"(a[2]), "r"(a[3]), "r"(b0), "r"(b1));
}

#define LDSM4(r, addr) \
    asm volatile("ldmatrix.sync.aligned.m8n8.x4.shared.b16 {%0,%1,%2,%3}, [%4];" \
                 : "=r"((r)[0]), "=r"((r)[1]), "=r"((r)[2]), "=r"((r)[3]) : "r"(addr))

// ---------------- smem layout (bytes) ----------------
// A bufs: 2 x (64 rows x 132 words x 4B = 33792)       = 67584
// B:      256 u-rows x 132 words x 4B                   = 135168
// srow:   64 x 8 floats                                 = 2048
#define SAW 132
#define ABUF_BYTES 33792
#define SM_A 0
#define SM_B (2 * ABUF_BYTES)
#define SM_SROW (SM_B + 135168)
#define SM_TOTAL (SM_SROW + 2048)

// ---------------- kernel 0: biasq[b,u] = W1_b + W2_b + query@W2 ----------------

__global__ __launch_bounds__(256)
void projq_kernel(const float* __restrict__ query, const float* __restrict__ W2,
                  const float* __restrict__ W2b, const float* __restrict__ W1b) {
    int u = threadIdx.x, b = blockIdx.x;
    __shared__ float q[Dn];
    if (u < Dn) q[u] = query[b * Dn + u];
    __syncthreads();
    float acc[8] = {0.f, 0.f, 0.f, 0.f, 0.f, 0.f, 0.f, 0.f};
#pragma unroll 4
    for (int d0 = 0; d0 < Dn; d0 += 8) {
#pragma unroll
        for (int j = 0; j < 8; ++j)
            acc[j] += q[d0 + j] * __ldg(W2 + (size_t)(d0 + j) * Un + u);
    }
    float s = ((acc[0] + acc[1]) + (acc[2] + acc[3])) + ((acc[4] + acc[5]) + (acc[6] + acc[7]));
    g_biasq[b * Un + u] = s + W2b[u] + W1b[u];
}

// ---------------- kernel 1: persistent, pipelined score kernel ----------------
// Grid 148 x 512 threads (16 warps). W1 staged once; per tile: M=64, K=256, N=256.
// Warp (mwarp=wid&1, nwarp=wid>>1) -> 32 rows x 32 cols: 2 mtiles x 4 ntiles m16n8k16.

__global__ __launch_bounds__(512, 1)
void score_kernel(const float* __restrict__ values, const float* __restrict__ W1,
                  const float* __restrict__ Vw) {
    extern __shared__ char smem[];
    uint32_t* sA = (uint32_t*)(smem + SM_A);
    uint32_t* sB = (uint32_t*)(smem + SM_B);
    float* srow = (float*)(smem + SM_SROW);

    const int tid = threadIdx.x;
    const int wid = tid >> 5, lane = tid & 31;
    const int mwarp = wid & 1, nwarp = wid >> 1;
    const int g = lane >> 2, tig = lane & 3;

    // Stage B once: W1[k][u] -> sB[u][kp] (half2 of k-pair).
#pragma unroll 4
    for (int i = tid; i < 256 * 128; i += 512) {
        int u = i & 255, kp = i >> 8;
        float x0 = __ldg(W1 + (size_t)(2 * kp) * Un + u);
        float x1 = __ldg(W1 + (size_t)(2 * kp + 1) * Un + u);
        sB[u * SAW + kp] = pack_half2(x0, x1);
    }

    // Per-thread epilogue constants: 8 Vw values for cols c = nwarp*32 + nt*8 + 2tig + {0,1}.
    float vw[8];
#pragma unroll
    for (int nt = 0; nt < 4; ++nt) {
        int c = nwarp * 32 + nt * 8 + 2 * tig;
        vw[2 * nt] = __ldg(Vw + c);
        vw[2 * nt + 1] = __ldg(Vw + c + 1);
    }

    // ldmatrix per-lane addresses (buffer 0 base; add buf offset later).
    const uint32_t sbA = smem_u32(sA), sbB = smem_u32(sB);
    const int t4 = lane >> 3, row_in = lane & 7;
    uint32_t adA[2];
#pragma unroll
    for (int mt = 0; mt < 2; ++mt) {
        int r = mwarp * 32 + mt * 16 + ((t4 & 1) << 3) + row_in;
        adA[mt] = sbA + (uint32_t)((r * SAW + ((t4 >> 1) << 2)) << 2);
    }
    uint32_t adB[2];
#pragma unroll
    for (int np = 0; np < 2; ++np) {
        int u = nwarp * 32 + np * 16 + ((t4 >> 1) << 3) + row_in;
        adB[np] = sbB + (uint32_t)((u * SAW + ((t4 & 1) << 2)) << 2);
    }

    // Prologue: stage A for first tile directly.
    {
        int tile = blockIdx.x;
        int b = tile >> 7, t0 = (tile & 127) * TM;
        const float2* v2 = (const float2*)(values + ((size_t)b * Tn + t0) * Dn);
#pragma unroll 4
        for (int i = tid; i < TM * 128; i += 512) {
            float2 x = v2[i];
            sA[(i >> 7) * SAW + (i & 127)] = pack_half2(x.x, x.y);
        }
    }
    __syncthreads();

    int bufi = 0;
    for (int tile = blockIdx.x; tile < NTILES; tile += GRID_SCORE) {
        const int b = tile >> 7;
        const int t0 = (tile & 127) * TM;
        const int ntile = tile + GRID_SCORE;
        const int has_next = ntile < NTILES;

        // Prefetch next tile's values into registers (overlaps MMA below).
        float2 pf[16];
        if (has_next) {
            const int nb = ntile >> 7, nt0 = (ntile & 127) * TM;
            const float2* v2 = (const float2*)(values + ((size_t)nb * Tn + nt0) * Dn);
#pragma unroll
            for (int j = 0; j < 16; ++j) pf[j] = __ldg(v2 + tid + j * 512);
        }

        // MMA over K=256 from buffer bufi.
        float acc[2][4][4];
#pragma unroll
        for (int mt = 0; mt < 2; ++mt)
#pragma unroll
            for (int nt = 0; nt < 4; ++nt)
#pragma unroll
                for (int q = 0; q < 4; ++q) acc[mt][nt][q] = 0.f;

        const uint32_t abase = (uint32_t)(bufi * ABUF_BYTES);
#pragma unroll
        for (int ks = 0; ks < 16; ++ks) {
            const uint32_t ko = (uint32_t)ks * 32;
            uint32_t a0[4], a1[4], b0[4], b1[4];
            LDSM4(a0, adA[0] + abase + ko);
            LDSM4(a1, adA[1] + abase + ko);
            LDSM4(b0, adB[0] + ko);
            LDSM4(b1, adB[1] + ko);
            mma_fp16(acc[0][0], a0, b0[0], b0[1]);
            mma_fp16(acc[1][0], a1, b0[0], b0[1]);
            mma_fp16(acc[0][1], a0, b0[2], b0[3]);
            mma_fp16(acc[1][1], a1, b0[2], b0[3]);
            mma_fp16(acc[0][2], a0, b1[0], b1[1]);
            mma_fp16(acc[1][2], a1, b1[0], b1[1]);
            mma_fp16(acc[0][3], a0, b1[2], b1[3]);
            mma_fp16(acc[1][3], a1, b1[2], b1[3]);
        }

        // Store prefetched tile into the other buffer.
        if (has_next) {
            uint32_t* dst = (uint32_t*)(smem + SM_A + (bufi ^ 1) * ABUF_BYTES);
#pragma unroll
            for (int j = 0; j < 16; ++j) {
                int i = tid + j * 512;
                dst[(i >> 7) * SAW + (i & 127)] = pack_half2(pf[j].x, pf[j].y);
            }
        }

        // Epilogue: tanh(p + biasq) * Vw over this warp's 32 cols.
        const float* bq = g_biasq + b * Un;
        float rowsum[2][2] = {{0.f, 0.f}, {0.f, 0.f}};
#pragma unroll
        for (int nt = 0; nt < 4; ++nt) {
            int c = nwarp * 32 + nt * 8 + 2 * tig;
            float bq0 = __ldg(bq + c), bq1 = __ldg(bq + c + 1);
#pragma unroll
            for (int mt = 0; mt < 2; ++mt) {
                rowsum[mt][0] += tanh_fast(acc[mt][nt][0] + bq0) * vw[2 * nt]
                               + tanh_fast(acc[mt][nt][1] + bq1) * vw[2 * nt + 1];
                rowsum[mt][1] += tanh_fast(acc[mt][nt][2] + bq0) * vw[2 * nt]
                               + tanh_fast(acc[mt][nt][3] + bq1) * vw[2 * nt + 1];
            }
        }
#pragma unroll
        for (int mt = 0; mt < 2; ++mt)
#pragma unroll
            for (int j = 0; j < 2; ++j) {
                float v = rowsum[mt][j];
                v += __shfl_xor_sync(0xffffffffu, v, 1);
                v += __shfl_xor_sync(0xffffffffu, v, 2);
                rowsum[mt][j] = v;
            }
        if (tig == 0) {
#pragma unroll
            for (int mt = 0; mt < 2; ++mt) {
                int row = mwarp * 32 + mt * 16 + g;
                srow[row * 8 + nwarp] = rowsum[mt][0];
                srow[(row + 8) * 8 + nwarp] = rowsum[mt][1];
            }
        }
        __syncthreads();
        if (tid < TM) {
            const float4* s4 = (const float4*)(srow + tid * 8);
            float4 x = s4[0], y = s4[1];
            float s = ((x.x + x.y) + (x.z + x.w)) + ((y.x + y.y) + (y.z + y.w));
            g_escore[b * Tn + t0 + tid] = __expf(s);
        }
        __syncthreads();
        bufi ^= 1;
    }
}

// ---------------- kernel 2: per-batch Z = sum(exp scores) ----------------

__global__ void stats_kernel() {
    int b = blockIdx.x, tid = threadIdx.x;
    __shared__ float red[8];
    const float* sc = g_escore + b * Tn;
    float s = 0.f;
#pragma unroll 8
    for (int i = tid; i < Tn; i += 256) s += sc[i];
#pragma unroll
    for (int o = 16; o; o >>= 1) s += __shfl_xor_sync(0xffffffffu, s, o);
    if ((tid & 31) == 0) red[tid >> 5] = s;
    __syncthreads();
    if (tid == 0) {
        float z = 0.f;
#pragma unroll
        for (int w = 0; w < 8; ++w) z += red[w];
        g_Z[b] = z;
    }
}

// ---------------- kernel 3: weights + context partials ----------------

__global__ __launch_bounds__(256)
void ctx_kernel(const float* __restrict__ values, float* __restrict__ wout) {
    int ch = blockIdx.x, b = blockIdx.y, tid = threadIdx.x;
    __shared__ float ws[128];
    __shared__ float4 spart[3][64];
    float invZ = 1.0f / g_Z[b];
    int t0 = ch * 128;

    if (tid < 128) {
        float w = g_escore[b * Tn + t0 + tid] * invZ;
        ws[tid] = w;
        wout[b * Tn + t0 + tid] = w;
    }
    __syncthreads();

    int g2 = tid >> 6, l64 = tid & 63;
    const float4* vp = (const float4*)(values + ((size_t)b * Tn + t0) * Dn);
    float4 acc = make_float4(0.f, 0.f, 0.f, 0.f);
#pragma unroll 8
    for (int i = 0; i < 32; ++i) {
        int t = g2 * 32 + i;
        float w = ws[t];
        float4 v = __ldcs(vp + (size_t)t * 64 + l64);
        acc.x += w * v.x; acc.y += w * v.y; acc.z += w * v.z; acc.w += w * v.w;
    }
    if (g2 > 0) spart[g2 - 1][l64] = acc;
    __syncthreads();
    if (g2 == 0) {
#pragma unroll
        for (int j = 0; j < 3; ++j) {
            float4 p = spart[j][l64];
            acc.x += p.x; acc.y += p.y; acc.z += p.z; acc.w += p.w;
        }
        *(float4*)(g_partial + ((size_t)(b * CCH + ch)) * Dn + 4 * l64) = acc;
    }
}

// ---------------- kernel 4: reduce partials ----------------

__global__ __launch_bounds__(64)
void reduce_kernel(float* __restrict__ ctx_out) {
    int b = blockIdx.y, d = blockIdx.x * 64 + threadIdx.x;
    const float* p = g_partial + b * CCH * Dn + d;
    float s = 0.f;
#pragma unroll
    for (int c = 0; c < CCH; ++c) s += p[c * Dn];
    ctx_out[b * Dn + d] = s;
}

// ---------------- launch ----------------

extern "C" void kernel_launch(void* const* d_in, const int* in_sizes, int n_in,
                              void* d_out, int out_size) {
    const float* values = (const float*)d_in[0];
    const float* query  = (const float*)d_in[1];
    const float* W1w    = (const float*)d_in[2];
    const float* W1b    = (const float*)d_in[3];
    const float* W2w    = (const float*)d_in[4];
    const float* W2b    = (const float*)d_in[5];
    const float* Vw     = (const float*)d_in[6];
    // d_in[7] = V_b: softmax-invariant constant, intentionally unused.
    (void)in_sizes; (void)n_in; (void)out_size;

    float* ctx_out = (float*)d_out;             // [B, D]
    float* w_out   = (float*)d_out + Bn * Dn;   // [B, T, 1]

    cudaFuncSetAttribute(score_kernel, cudaFuncAttributeMaxDynamicSharedMemorySize, SM_TOTAL);

    projq_kernel<<<Bn, 256>>>(query, W2w, W2b, W1b);
    score_kernel<<<GRID_SCORE, 512, SM_TOTAL>>>(values, W1w, Vw);
    stats_kernel<<<Bn, 256>>>();
    ctx_kernel<<<dim3(CCH, Bn), 256>>>(values, w_out);
    reduce_kernel<<<dim3(4, Bn), 64>>>(ctx_out);
}